// round 6
// baseline (speedup 1.0000x reference)
#include <cuda_runtime.h>

#define B_   4
#define T_   2048
#define C_   768
#define H_   12
#define D_   64
#define BH_  48
#define M_   8192
#define N3_  2304

// ---- scratch (device globals) ----
// All MMA k-dims stored gmem-permuted: within each 8-group, slot(k) = (k&3)*2 + (k>>2)
__device__ float g_xr[M_ * C_];      // x: rounded + k-permuted
__device__ float g_wat[N3_ * C_];    // w_attn^T, k-permuted
__device__ float g_wpt[C_ * C_];     // w_proj^T, k-permuted
__device__ float g_q[BH_ * T_ * D_]; // [bh][t][d-perm] *0.125 tf32
__device__ float g_k[BH_ * T_ * D_]; // [bh][t][d-perm] tf32
__device__ float g_vt[BH_ * D_ * T_];// [bh][d][t-perm] tf32
__device__ float g_y[M_ * C_];       // [m][c-perm] tf32

__device__ __forceinline__ float rna(float x) {
    unsigned r; asm("cvt.rna.tf32.f32 %0, %1;" : "=r"(r) : "f"(x));
    return __uint_as_float(r);
}
__device__ __forceinline__ unsigned fau(float x) { return __float_as_uint(x); }

__device__ __forceinline__ void mma8(float* c,
    unsigned a0, unsigned a1, unsigned a2, unsigned a3,
    unsigned b0, unsigned b1)
{
    asm volatile(
      "mma.sync.aligned.m16n8k8.row.col.f32.tf32.tf32.f32 "
      "{%0,%1,%2,%3},{%4,%5,%6,%7},{%8,%9},{%0,%1,%2,%3};"
      : "+f"(c[0]), "+f"(c[1]), "+f"(c[2]), "+f"(c[3])
      : "r"(a0), "r"(a1), "r"(a2), "r"(a3), "r"(b0), "r"(b1));
}

__device__ __forceinline__ void cp16(float* dst_smem, const float* src) {
    unsigned d = (unsigned)__cvta_generic_to_shared(dst_smem);
    asm volatile("cp.async.ca.shared.global [%0], [%1], 16;" :: "r"(d), "l"(src));
}
#define CP_COMMIT asm volatile("cp.async.commit_group;" ::: "memory")
#define CP_WAIT0  asm volatile("cp.async.wait_group 0;" ::: "memory")
#define CP_WAIT1  asm volatile("cp.async.wait_group 1;" ::: "memory")

// ---------------------------------------------------------------------------
// Prep: round x to tf32 + permute k within 8-groups (slots hold k = 0,4,1,5,2,6,3,7)
// ---------------------------------------------------------------------------
__global__ void roundperm_kernel(const float* __restrict__ in, float* __restrict__ out, int n8)
{
    for (int i = blockIdx.x * blockDim.x + threadIdx.x; i < n8; i += gridDim.x * blockDim.x) {
        float4 a = ((const float4*)in)[2 * i];
        float4 b = ((const float4*)in)[2 * i + 1];
        ((float4*)out)[2 * i]     = make_float4(rna(a.x), rna(b.x), rna(a.y), rna(b.y));
        ((float4*)out)[2 * i + 1] = make_float4(rna(a.z), rna(b.z), rna(a.w), rna(b.w));
    }
}

// Prep: transpose + round + k-permute. in [R][Cc] -> out [Cc][R(perm)]
__global__ void transpose_round_kernel(const float* __restrict__ in, float* __restrict__ out,
                                       int R, int Cc)
{
    __shared__ float tile[32][33];
    int bx = blockIdx.x * 32, by = blockIdx.y * 32;
    int x = bx + threadIdx.x;
    #pragma unroll
    for (int j = threadIdx.y; j < 32; j += 8)
        tile[j][threadIdx.x] = in[(by + j) * Cc + x];
    __syncthreads();
    int ox = by + threadIdx.x;
    int oxp = (ox & ~7) | (((ox & 3) << 1) | ((ox & 7) >> 2));
    #pragma unroll
    for (int j = threadIdx.y; j < 32; j += 8)
        out[(bx + j) * R + oxp] = rna(tile[threadIdx.x][j]);
}

// ---------------------------------------------------------------------------
// tf32 GEMM, 128x128 block, 8 warps (4m x 2n), warp tile 32x64, k-step 32.
// 3-stage cp.async pipeline (wait_group 1), pre-permuted operands,
// 1 barrier per k-step, pitch 36.
// ---------------------------------------------------------------------------
#define GP 36
#define GA (128 * GP)
#define GEMM_SMEM (6 * GA * 4)   // 3 bufs x (A+B) = 110592 B -> 2 CTAs/SM

__global__ __launch_bounds__(256, 2) void gemm_kernel(
    const float* __restrict__ A, const float* __restrict__ Bt,
    const float* __restrict__ bias, float* __restrict__ out, int mode)
{
    extern __shared__ float sm[];
    float* sAb = sm;            // 3 buffers
    float* sBb = sm + 3 * GA;   // 3 buffers

    const int m0 = blockIdx.y * 128;
    const int n0 = blockIdx.x * 128;
    const int tid = threadIdx.x;
    const int warp = tid >> 5, lane = tid & 31;
    const int g = lane >> 2, tig = lane & 3;
    const int wm = warp & 3, wn = warp >> 2;

    const int srow = tid >> 1;
    const int scol = (tid & 1) * 16;

    const float* Ap = A  + (long)(m0 + srow) * C_ + scol;
    const float* Bp = Bt + (long)(n0 + srow) * C_ + scol;

    float acc[2][8][4] = {};

#define GISSUE(buf, ks) do { \
    const float* ga_ = Ap + (ks) * 32; \
    const float* gb_ = Bp + (ks) * 32; \
    float* dA_ = sAb + (buf) * GA + srow * GP + scol; \
    float* dB_ = sBb + (buf) * GA + srow * GP + scol; \
    _Pragma("unroll") \
    for (int j_ = 0; j_ < 4; ++j_) { cp16(dA_ + j_ * 4, ga_ + j_ * 4); \
                                     cp16(dB_ + j_ * 4, gb_ + j_ * 4); } \
} while (0)

    GISSUE(0, 0); CP_COMMIT;
    GISSUE(1, 1); CP_COMMIT;

    const int NS = C_ / 32;  // 24 (multiple of 3)
    int buf = 0;
    for (int ks = 0; ks < NS; ++ks) {
        CP_WAIT1;            // group for 'buf' is done; next group may be in flight
        __syncthreads();
        if (ks + 2 < NS) {
            int nbuf = buf + 2; if (nbuf >= 3) nbuf -= 3;
            GISSUE(nbuf, ks + 2); CP_COMMIT;
        }

        const float* cA = sAb + buf * GA;
        const float* cB = sBb + buf * GA;
        #pragma unroll
        for (int kf = 0; kf < 4; ++kf) {
            unsigned a[2][4];
            #pragma unroll
            for (int mf = 0; mf < 2; ++mf) {
                const float* p = cA + (wm * 32 + mf * 16) * GP + kf * 8 + 2 * tig;
                float2 x0 = *(const float2*)(p + g * GP);
                float2 x1 = *(const float2*)(p + (g + 8) * GP);
                a[mf][0] = fau(x0.x); a[mf][1] = fau(x1.x);
                a[mf][2] = fau(x0.y); a[mf][3] = fau(x1.y);
            }
            #pragma unroll
            for (int nt = 0; nt < 8; ++nt) {
                float2 bv = *(const float2*)(cB + (wn * 64 + nt * 8 + g) * GP + kf * 8 + 2 * tig);
                unsigned b0 = fau(bv.x), b1 = fau(bv.y);
                mma8(acc[0][nt], a[0][0], a[0][1], a[0][2], a[0][3], b0, b1);
                mma8(acc[1][nt], a[1][0], a[1][1], a[1][2], a[1][3], b0, b1);
            }
        }
        if (++buf == 3) buf = 0;
        // no trailing barrier: next iteration's wait+barrier separates
        // this iteration's reads from the cp.async that overwrites them.
    }

    const int c0 = 2 * tig, c1 = 2 * tig + 1;
    const int s0 = ((c0 & 3) << 1) | (c0 >> 2);
    const int s1 = ((c1 & 3) << 1) | (c1 >> 2);

    if (mode == 1) {
        #pragma unroll
        for (int mf = 0; mf < 2; ++mf) {
            int r = m0 + wm * 32 + mf * 16 + g;
            #pragma unroll
            for (int nt = 0; nt < 8; ++nt) {
                int c = n0 + wn * 64 + nt * 8 + c0;
                float b0 = bias[c], b1 = bias[c + 1];
                *(float2*)(out + (long)r * C_ + c) =
                    make_float2(acc[mf][nt][0] + b0, acc[mf][nt][1] + b1);
                *(float2*)(out + (long)(r + 8) * C_ + c) =
                    make_float2(acc[mf][nt][2] + b0, acc[mf][nt][3] + b1);
            }
        }
        return;
    }

    // QKV scatter epilogue (permuted destinations)
    const int ncw   = n0 + wn * 64;
    const int which = ncw / C_;
    const int hh    = (ncw % C_) >> 6;
    const int bb    = m0 >> 11;
    const int t0    = m0 & (T_ - 1);
    const int bh    = bb * H_ + hh;
    const int sg    = ((g & 3) << 1) | (g >> 2);   // t-slot for g_vt

    #pragma unroll
    for (int mf = 0; mf < 2; ++mf) {
        int t = t0 + wm * 32 + mf * 16 + g;
        int tp = (t - g) + sg;
        #pragma unroll
        for (int nt = 0; nt < 8; ++nt) {
            int d8 = nt * 8;
            float b0 = bias[ncw + d8 + c0], b1 = bias[ncw + d8 + c1];
            float v0 = acc[mf][nt][0] + b0, v1 = acc[mf][nt][1] + b1;
            float v2 = acc[mf][nt][2] + b0, v3 = acc[mf][nt][3] + b1;
            if (which == 0) {
                float* p0 = g_q + ((long)bh * T_ + t) * D_ + d8;
                p0[s0] = rna(v0 * 0.125f); p0[s1] = rna(v1 * 0.125f);
                float* p1 = p0 + 8 * D_;
                p1[s0] = rna(v2 * 0.125f); p1[s1] = rna(v3 * 0.125f);
            } else if (which == 1) {
                float* p0 = g_k + ((long)bh * T_ + t) * D_ + d8;
                p0[s0] = rna(v0); p0[s1] = rna(v1);
                float* p1 = p0 + 8 * D_;
                p1[s0] = rna(v2); p1[s1] = rna(v3);
            } else {
                g_vt[((long)bh * D_ + d8 + c0) * T_ + tp]     = rna(v0);
                g_vt[((long)bh * D_ + d8 + c1) * T_ + tp]     = rna(v1);
                g_vt[((long)bh * D_ + d8 + c0) * T_ + tp + 8] = rna(v2);
                g_vt[((long)bh * D_ + d8 + c1) * T_ + tp + 8] = rna(v3);
            }
        }
    }
}

// ---------------------------------------------------------------------------
// Flash attention: 8 warps x 16 q-rows = 128 queries/block, K-tile 64,
// cp.async double-buffered K/V, heavy-first block order, 1 barrier per tile.
// ---------------------------------------------------------------------------
#define AP 72
#define KBUF (64 * AP)
#define ATT_SMEM ((4 * KBUF + 128 * AP) * 4)   // 110592 B

__global__ __launch_bounds__(256, 2) void attn_kernel()
{
    extern __shared__ float sm[];
    float* sK = sm;                 // 2 buffers
    float* sV = sm + 2 * KBUF;      // 2 buffers
    float* sP = sm + 4 * KBUF;

    const int qb = gridDim.x - 1 - blockIdx.x;   // heavy blocks first
    const int bh = blockIdx.y;
    const int bb = bh / H_, hh = bh % H_;
    const int q0 = qb * 128;
    const int tid = threadIdx.x;
    const int warp = tid >> 5, lane = tid & 31;
    const int g = lane >> 2, tig = lane & 3;

    const int srow = tid >> 2;
    const int scol = (tid & 3) * 16;

    const float* Kg = g_k  + ((long)bh * T_ + srow) * D_ + scol;
    const float* Vg = g_vt + ((long)bh * D_ + srow) * T_ + scol;

#define AISSUE(buf, kt) do { \
    const float* ks_ = Kg + (kt) * 64 * D_; \
    const float* vs_ = Vg + (kt) * 64; \
    float* kd_ = sK + (buf) * KBUF + srow * AP + scol; \
    float* vd_ = sV + (buf) * KBUF + srow * AP + scol; \
    _Pragma("unroll") \
    for (int j_ = 0; j_ < 4; ++j_) { cp16(kd_ + j_ * 4, ks_ + j_ * 4); \
                                     cp16(vd_ + j_ * 4, vs_ + j_ * 4); } \
} while (0)

    AISSUE(0, 0); CP_COMMIT;

    // Q fragments in registers (gmem already scaled, rounded, d-permuted)
    unsigned qf[8][4];
    {
        const float* r0 = g_q + ((long)bh * T_ + q0 + warp * 16 + g) * D_;
        const float* r1 = r0 + 8 * D_;
        #pragma unroll
        for (int kf = 0; kf < 8; ++kf) {
            float2 q0v = *(const float2*)(r0 + kf * 8 + 2 * tig);
            float2 q1v = *(const float2*)(r1 + kf * 8 + 2 * tig);
            qf[kf][0] = fau(q0v.x); qf[kf][2] = fau(q0v.y);
            qf[kf][1] = fau(q1v.x); qf[kf][3] = fau(q1v.y);
        }
    }

    float oacc[8][4] = {};
    float m0s = -1e30f, m1s = -1e30f, l0s = 0.0f, l1s = 0.0f;

    const int c0 = 2 * tig, c1 = 2 * tig + 1;
    const int s0 = ((c0 & 3) << 1) | (c0 >> 2);
    const int s1 = ((c1 & 3) << 1) | (c1 >> 2);
    const int prow = warp * 16 + g;

    const int ktmax = 2 * qb + 1;
    for (int kt = 0; kt <= ktmax; ++kt) {
        CP_WAIT0;
        __syncthreads();
        if (kt < ktmax) { AISSUE((kt + 1) & 1, kt + 1); CP_COMMIT; }

        const float* cK = sK + (kt & 1) * KBUF;
        const float* cV = sV + (kt & 1) * KBUF;

        // S = Q @ K^T (warp: 16 x 64)
        float sacc[8][4] = {};
        #pragma unroll
        for (int kf = 0; kf < 8; ++kf) {
            #pragma unroll
            for (int nt = 0; nt < 8; ++nt) {
                float2 bv = *(const float2*)(cK + (nt * 8 + g) * AP + kf * 8 + 2 * tig);
                mma8(sacc[nt], qf[kf][0], qf[kf][1], qf[kf][2], qf[kf][3],
                     fau(bv.x), fau(bv.y));
            }
        }

        const int rbase = q0 + warp * 16 + g;
        if (kt >= 2 * qb) {
            #pragma unroll
            for (int nt = 0; nt < 8; ++nt) {
                int cb = kt * 64 + nt * 8 + c0;
                if (cb     > rbase)     sacc[nt][0] = -1e30f;
                if (cb + 1 > rbase)     sacc[nt][1] = -1e30f;
                if (cb     > rbase + 8) sacc[nt][2] = -1e30f;
                if (cb + 1 > rbase + 8) sacc[nt][3] = -1e30f;
            }
        }

        float mx0 = -1e30f, mx1 = -1e30f;
        #pragma unroll
        for (int nt = 0; nt < 8; ++nt) {
            mx0 = fmaxf(mx0, fmaxf(sacc[nt][0], sacc[nt][1]));
            mx1 = fmaxf(mx1, fmaxf(sacc[nt][2], sacc[nt][3]));
        }
        mx0 = fmaxf(mx0, __shfl_xor_sync(0xffffffffu, mx0, 1));
        mx0 = fmaxf(mx0, __shfl_xor_sync(0xffffffffu, mx0, 2));
        mx1 = fmaxf(mx1, __shfl_xor_sync(0xffffffffu, mx1, 1));
        mx1 = fmaxf(mx1, __shfl_xor_sync(0xffffffffu, mx1, 2));

        float mn0 = fmaxf(m0s, mx0), mn1 = fmaxf(m1s, mx1);
        float al0 = __expf(m0s - mn0), al1 = __expf(m1s - mn1);
        m0s = mn0; m1s = mn1;

        float sum0 = 0.0f, sum1 = 0.0f;
        #pragma unroll
        for (int nt = 0; nt < 8; ++nt) {
            float p0 = __expf(sacc[nt][0] - mn0);
            float p1 = __expf(sacc[nt][1] - mn0);
            float p2 = __expf(sacc[nt][2] - mn1);
            float p3 = __expf(sacc[nt][3] - mn1);
            sum0 += p0 + p1; sum1 += p2 + p3;
            float* pr0 = sP + prow * AP + nt * 8;
            float* pr1 = sP + (prow + 8) * AP + nt * 8;
            pr0[s0] = rna(p0); pr0[s1] = rna(p1);
            pr1[s0] = rna(p2); pr1[s1] = rna(p3);
        }
        sum0 += __shfl_xor_sync(0xffffffffu, sum0, 1);
        sum0 += __shfl_xor_sync(0xffffffffu, sum0, 2);
        sum1 += __shfl_xor_sync(0xffffffffu, sum1, 1);
        sum1 += __shfl_xor_sync(0xffffffffu, sum1, 2);
        l0s = l0s * al0 + sum0;
        l1s = l1s * al1 + sum1;
        #pragma unroll
        for (int nt = 0; nt < 8; ++nt) {
            oacc[nt][0] *= al0; oacc[nt][1] *= al0;
            oacc[nt][2] *= al1; oacc[nt][3] *= al1;
        }
        __syncwarp();   // sP is warp-private: warp-level fence suffices

        // O += P @ V
        #pragma unroll
        for (int kf = 0; kf < 8; ++kf) {
            const float* p = sP + (warp * 16) * AP + kf * 8 + 2 * tig;
            float2 x0 = *(const float2*)(p + g * AP);
            float2 x1 = *(const float2*)(p + (g + 8) * AP);
            unsigned a0 = fau(x0.x), a1 = fau(x1.x), a2 = fau(x0.y), a3 = fau(x1.y);
            #pragma unroll
            for (int nt = 0; nt < 8; ++nt) {
                float2 bv = *(const float2*)(cV + (nt * 8 + g) * AP + kf * 8 + 2 * tig);
                mma8(oacc[nt], a0, a1, a2, a3, fau(bv.x), fau(bv.y));
            }
        }
        // no trailing barrier (same argument as the GEMM loop)
    }

    // epilogue -> g_y (tf32-rounded, c-permuted for proj GEMM)
    const int row = q0 + warp * 16 + g;
    const float inv0 = 1.0f / l0s, inv1 = 1.0f / l1s;
    #pragma unroll
    for (int nt = 0; nt < 8; ++nt) {
        int colb = hh * 64 + nt * 8;
        float* y0 = g_y + ((long)bb * T_ + row) * C_ + colb;
        float* y1 = g_y + ((long)bb * T_ + row + 8) * C_ + colb;
        y0[s0] = rna(oacc[nt][0] * inv0); y0[s1] = rna(oacc[nt][1] * inv0);
        y1[s0] = rna(oacc[nt][2] * inv1); y1[s1] = rna(oacc[nt][3] * inv1);
    }
}

// ---------------------------------------------------------------------------
extern "C" void kernel_launch(void* const* d_in, const int* in_sizes, int n_in,
                              void* d_out, int out_size)
{
    const float* x      = (const float*)d_in[0];
    const float* w_attn = (const float*)d_in[1];
    const float* b_attn = (const float*)d_in[2];
    const float* w_proj = (const float*)d_in[3];
    const float* b_proj = (const float*)d_in[4];
    float* out = (float*)d_out;

    float *xr, *wat, *wpt, *yy;
    cudaGetSymbolAddress((void**)&xr,  g_xr);
    cudaGetSymbolAddress((void**)&wat, g_wat);
    cudaGetSymbolAddress((void**)&wpt, g_wpt);
    cudaGetSymbolAddress((void**)&yy,  g_y);

    cudaFuncSetAttribute(gemm_kernel,
                         cudaFuncAttributeMaxDynamicSharedMemorySize, GEMM_SMEM);
    cudaFuncSetAttribute(attn_kernel,
                         cudaFuncAttributeMaxDynamicSharedMemorySize, ATT_SMEM);

    roundperm_kernel<<<512, 256>>>(x, xr, M_ * C_ / 8);
    transpose_round_kernel<<<dim3(N3_ / 32, C_ / 32), dim3(32, 8)>>>(w_attn, wat, C_, N3_);
    transpose_round_kernel<<<dim3(C_ / 32, C_ / 32), dim3(32, 8)>>>(w_proj, wpt, C_, C_);

    gemm_kernel<<<dim3(N3_ / 128, M_ / 128), 256, GEMM_SMEM>>>(xr, wat, b_attn, nullptr, 0);
    attn_kernel<<<dim3(T_ / 128, BH_), 256, ATT_SMEM>>>();
    gemm_kernel<<<dim3(C_ / 128, M_ / 128), 256, GEMM_SMEM>>>(yy, wpt, b_proj, out, 1);
}

// round 8
// speedup vs baseline: 1.8070x; 1.8070x over previous
#include <cuda_runtime.h>

#define B_   4
#define T_   2048
#define C_   768
#define H_   12
#define D_   64
#define BH_  48
#define M_   8192
#define N3_  2304

// ---- scratch (device globals) ----
// All MMA k-dims stored gmem-permuted: within each 8-group, slot(k) = (k&3)*2 + (k>>2)
__device__ float g_xr[M_ * C_];      // x: rounded + k-permuted
__device__ float g_wat[N3_ * C_];    // w_attn^T, k-permuted
__device__ float g_wpt[C_ * C_];     // w_proj^T, k-permuted
__device__ float g_q[BH_ * T_ * D_]; // [bh][t][d-perm] *0.125 tf32
__device__ float g_k[BH_ * T_ * D_]; // [bh][t][d-perm] tf32
__device__ float g_vt[BH_ * D_ * T_];// [bh][d][t-perm] tf32
__device__ float g_y[M_ * C_];       // [m][c-perm] tf32

__device__ __forceinline__ float rna(float x) {
    unsigned r; asm("cvt.rna.tf32.f32 %0, %1;" : "=r"(r) : "f"(x));
    return __uint_as_float(r);
}
__device__ __forceinline__ unsigned fau(float x) { return __float_as_uint(x); }

__device__ __forceinline__ void mma8(float* c,
    unsigned a0, unsigned a1, unsigned a2, unsigned a3,
    unsigned b0, unsigned b1)
{
    asm volatile(
      "mma.sync.aligned.m16n8k8.row.col.f32.tf32.tf32.f32 "
      "{%0,%1,%2,%3},{%4,%5,%6,%7},{%8,%9},{%0,%1,%2,%3};"
      : "+f"(c[0]), "+f"(c[1]), "+f"(c[2]), "+f"(c[3])
      : "r"(a0), "r"(a1), "r"(a2), "r"(a3), "r"(b0), "r"(b1));
}

__device__ __forceinline__ void cp16(float* dst_smem, const float* src) {
    unsigned d = (unsigned)__cvta_generic_to_shared(dst_smem);
    asm volatile("cp.async.ca.shared.global [%0], [%1], 16;" :: "r"(d), "l"(src));
}
#define CP_COMMIT asm volatile("cp.async.commit_group;" ::: "memory")
#define CP_WAIT0  asm volatile("cp.async.wait_group 0;" ::: "memory")

// ---------------------------------------------------------------------------
// Prep: round x to tf32 + permute k within 8-groups (slots hold k = 0,4,1,5,2,6,3,7)
// ---------------------------------------------------------------------------
__global__ void roundperm_kernel(const float* __restrict__ in, float* __restrict__ out, int n8)
{
    for (int i = blockIdx.x * blockDim.x + threadIdx.x; i < n8; i += gridDim.x * blockDim.x) {
        float4 a = ((const float4*)in)[2 * i];
        float4 b = ((const float4*)in)[2 * i + 1];
        ((float4*)out)[2 * i]     = make_float4(rna(a.x), rna(b.x), rna(a.y), rna(b.y));
        ((float4*)out)[2 * i + 1] = make_float4(rna(a.z), rna(b.z), rna(a.w), rna(b.w));
    }
}

// Prep: transpose + round + k-permute. in [R][Cc] -> out [Cc][R(perm)]
__global__ void transpose_round_kernel(const float* __restrict__ in, float* __restrict__ out,
                                       int R, int Cc)
{
    __shared__ float tile[32][33];
    int bx = blockIdx.x * 32, by = blockIdx.y * 32;
    int x = bx + threadIdx.x;
    #pragma unroll
    for (int j = threadIdx.y; j < 32; j += 8)
        tile[j][threadIdx.x] = in[(by + j) * Cc + x];
    __syncthreads();
    int ox = by + threadIdx.x;
    int oxp = (ox & ~7) | (((ox & 3) << 1) | ((ox & 7) >> 2));
    #pragma unroll
    for (int j = threadIdx.y; j < 32; j += 8)
        out[(bx + j) * R + oxp] = rna(tile[threadIdx.x][j]);
}

// ---------------------------------------------------------------------------
// tf32 GEMM, 128x128 block, 8 warps (4m x 2n), warp tile 32x64, k-step 32.
// cp.async double-buffered staging of pre-permuted operands. Pitch 40
// (g*8+2*tig covers all 32 banks per 16-thread phase: conflict-free).
// ---------------------------------------------------------------------------
#define GP 40
#define GA (128 * GP)
#define GEMM_SMEM (4 * GA * 4)   // 81920 B -> 2 CTAs/SM

__global__ __launch_bounds__(256, 2) void gemm_kernel(
    const float* __restrict__ A, const float* __restrict__ Bt,
    const float* __restrict__ bias, float* __restrict__ out, int mode)
{
    extern __shared__ float sm[];
    float* sAb = sm;
    float* sBb = sm + 2 * GA;

    const int m0 = blockIdx.y * 128;
    const int n0 = blockIdx.x * 128;
    const int tid = threadIdx.x;
    const int warp = tid >> 5, lane = tid & 31;
    const int g = lane >> 2, tig = lane & 3;
    const int wm = warp & 3, wn = warp >> 2;

    const int srow = tid >> 1;
    const int scol = (tid & 1) * 16;

    const float* Ap = A  + (long)(m0 + srow) * C_ + scol;
    const float* Bp = Bt + (long)(n0 + srow) * C_ + scol;

    float acc[2][8][4] = {};

#define GISSUE(buf, ks) do { \
    const float* ga_ = Ap + (ks) * 32; \
    const float* gb_ = Bp + (ks) * 32; \
    float* dA_ = sAb + (buf) * GA + srow * GP + scol; \
    float* dB_ = sBb + (buf) * GA + srow * GP + scol; \
    _Pragma("unroll") \
    for (int j_ = 0; j_ < 4; ++j_) { cp16(dA_ + j_ * 4, ga_ + j_ * 4); \
                                     cp16(dB_ + j_ * 4, gb_ + j_ * 4); } \
} while (0)

    GISSUE(0, 0); CP_COMMIT;

    const int NS = C_ / 32;  // 24
    for (int ks = 0; ks < NS; ++ks) {
        CP_WAIT0;
        __syncthreads();
        if (ks + 1 < NS) { GISSUE((ks + 1) & 1, ks + 1); CP_COMMIT; }

        const float* cA = sAb + (ks & 1) * GA;
        const float* cB = sBb + (ks & 1) * GA;
        #pragma unroll
        for (int kf = 0; kf < 4; ++kf) {
            unsigned a[2][4];
            #pragma unroll
            for (int mf = 0; mf < 2; ++mf) {
                const float* p = cA + (wm * 32 + mf * 16) * GP + kf * 8 + 2 * tig;
                float2 x0 = *(const float2*)(p + g * GP);
                float2 x1 = *(const float2*)(p + (g + 8) * GP);
                a[mf][0] = fau(x0.x); a[mf][1] = fau(x1.x);
                a[mf][2] = fau(x0.y); a[mf][3] = fau(x1.y);
            }
            #pragma unroll
            for (int nt = 0; nt < 8; ++nt) {
                float2 bv = *(const float2*)(cB + (wn * 64 + nt * 8 + g) * GP + kf * 8 + 2 * tig);
                unsigned b0 = fau(bv.x), b1 = fau(bv.y);
                mma8(acc[0][nt], a[0][0], a[0][1], a[0][2], a[0][3], b0, b1);
                mma8(acc[1][nt], a[1][0], a[1][1], a[1][2], a[1][3], b0, b1);
            }
        }
        // no trailing barrier: next iteration's wait+barrier separates
        // this iteration's reads from the cp.async that overwrites them.
    }

    const int c0 = 2 * tig, c1 = 2 * tig + 1;
    const int s0 = ((c0 & 3) << 1) | (c0 >> 2);
    const int s1 = ((c1 & 3) << 1) | (c1 >> 2);

    if (mode == 1) {
        #pragma unroll
        for (int mf = 0; mf < 2; ++mf) {
            int r = m0 + wm * 32 + mf * 16 + g;
            #pragma unroll
            for (int nt = 0; nt < 8; ++nt) {
                int c = n0 + wn * 64 + nt * 8 + c0;
                float b0 = bias[c], b1 = bias[c + 1];
                *(float2*)(out + (long)r * C_ + c) =
                    make_float2(acc[mf][nt][0] + b0, acc[mf][nt][1] + b1);
                *(float2*)(out + (long)(r + 8) * C_ + c) =
                    make_float2(acc[mf][nt][2] + b0, acc[mf][nt][3] + b1);
            }
        }
        return;
    }

    // QKV scatter epilogue (permuted destinations)
    const int ncw   = n0 + wn * 64;
    const int which = ncw / C_;
    const int hh    = (ncw % C_) >> 6;
    const int bb    = m0 >> 11;
    const int t0    = m0 & (T_ - 1);
    const int bh    = bb * H_ + hh;
    const int sg    = ((g & 3) << 1) | (g >> 2);   // t-slot for g_vt

    #pragma unroll
    for (int mf = 0; mf < 2; ++mf) {
        int t = t0 + wm * 32 + mf * 16 + g;
        int tp = (t - g) + sg;
        #pragma unroll
        for (int nt = 0; nt < 8; ++nt) {
            int d8 = nt * 8;
            float b0 = bias[ncw + d8 + c0], b1 = bias[ncw + d8 + c1];
            float v0 = acc[mf][nt][0] + b0, v1 = acc[mf][nt][1] + b1;
            float v2 = acc[mf][nt][2] + b0, v3 = acc[mf][nt][3] + b1;
            if (which == 0) {
                float* p0 = g_q + ((long)bh * T_ + t) * D_ + d8;
                p0[s0] = rna(v0 * 0.125f); p0[s1] = rna(v1 * 0.125f);
                float* p1 = p0 + 8 * D_;
                p1[s0] = rna(v2 * 0.125f); p1[s1] = rna(v3 * 0.125f);
            } else if (which == 1) {
                float* p0 = g_k + ((long)bh * T_ + t) * D_ + d8;
                p0[s0] = rna(v0); p0[s1] = rna(v1);
                float* p1 = p0 + 8 * D_;
                p1[s0] = rna(v2); p1[s1] = rna(v3);
            } else {
                g_vt[((long)bh * D_ + d8 + c0) * T_ + tp]     = rna(v0);
                g_vt[((long)bh * D_ + d8 + c1) * T_ + tp]     = rna(v1);
                g_vt[((long)bh * D_ + d8 + c0) * T_ + tp + 8] = rna(v2);
                g_vt[((long)bh * D_ + d8 + c1) * T_ + tp + 8] = rna(v3);
            }
        }
    }
}

// ---------------------------------------------------------------------------
// Flash attention: 8 warps x 16 q-rows = 128 queries/block, K-tile 64,
// cp.async double-buffered K/V, heavy-first block order.
// ---------------------------------------------------------------------------
#define AP 72
#define KBUF (64 * AP)
#define ATT_SMEM ((4 * KBUF + 128 * AP) * 4)   // 110592 B

__global__ __launch_bounds__(256, 2) void attn_kernel()
{
    extern __shared__ float sm[];
    float* sK = sm;                 // 2 buffers
    float* sV = sm + 2 * KBUF;      // 2 buffers
    float* sP = sm + 4 * KBUF;

    const int qb = gridDim.x - 1 - blockIdx.x;   // heavy blocks first
    const int bh = blockIdx.y;
    const int bb = bh / H_, hh = bh % H_;
    const int q0 = qb * 128;
    const int tid = threadIdx.x;
    const int warp = tid >> 5, lane = tid & 31;
    const int g = lane >> 2, tig = lane & 3;

    const int srow = tid >> 2;
    const int scol = (tid & 3) * 16;

    const float* Kg = g_k  + ((long)bh * T_ + srow) * D_ + scol;
    const float* Vg = g_vt + ((long)bh * D_ + srow) * T_ + scol;

#define AISSUE(buf, kt) do { \
    const float* ks_ = Kg + (kt) * 64 * D_; \
    const float* vs_ = Vg + (kt) * 64; \
    float* kd_ = sK + (buf) * KBUF + srow * AP + scol; \
    float* vd_ = sV + (buf) * KBUF + srow * AP + scol; \
    _Pragma("unroll") \
    for (int j_ = 0; j_ < 4; ++j_) { cp16(kd_ + j_ * 4, ks_ + j_ * 4); \
                                     cp16(vd_ + j_ * 4, vs_ + j_ * 4); } \
} while (0)

    AISSUE(0, 0); CP_COMMIT;

    // Q fragments in registers (gmem already scaled, rounded, d-permuted)
    unsigned qf[8][4];
    {
        const float* r0 = g_q + ((long)bh * T_ + q0 + warp * 16 + g) * D_;
        const float* r1 = r0 + 8 * D_;
        #pragma unroll
        for (int kf = 0; kf < 8; ++kf) {
            float2 q0v = *(const float2*)(r0 + kf * 8 + 2 * tig);
            float2 q1v = *(const float2*)(r1 + kf * 8 + 2 * tig);
            qf[kf][0] = fau(q0v.x); qf[kf][2] = fau(q0v.y);
            qf[kf][1] = fau(q1v.x); qf[kf][3] = fau(q1v.y);
        }
    }

    float oacc[8][4] = {};
    float m0s = -1e30f, m1s = -1e30f, l0s = 0.0f, l1s = 0.0f;

    const int c0 = 2 * tig, c1 = 2 * tig + 1;
    const int s0 = ((c0 & 3) << 1) | (c0 >> 2);
    const int s1 = ((c1 & 3) << 1) | (c1 >> 2);
    const int prow = warp * 16 + g;

    const int ktmax = 2 * qb + 1;
    for (int kt = 0; kt <= ktmax; ++kt) {
        CP_WAIT0;
        __syncthreads();
        if (kt < ktmax) { AISSUE((kt + 1) & 1, kt + 1); CP_COMMIT; }

        const float* cK = sK + (kt & 1) * KBUF;
        const float* cV = sV + (kt & 1) * KBUF;

        // S = Q @ K^T (warp: 16 x 64)
        float sacc[8][4] = {};
        #pragma unroll
        for (int kf = 0; kf < 8; ++kf) {
            #pragma unroll
            for (int nt = 0; nt < 8; ++nt) {
                float2 bv = *(const float2*)(cK + (nt * 8 + g) * AP + kf * 8 + 2 * tig);
                mma8(sacc[nt], qf[kf][0], qf[kf][1], qf[kf][2], qf[kf][3],
                     fau(bv.x), fau(bv.y));
            }
        }

        const int rbase = q0 + warp * 16 + g;
        if (kt >= 2 * qb) {
            #pragma unroll
            for (int nt = 0; nt < 8; ++nt) {
                int cb = kt * 64 + nt * 8 + c0;
                if (cb     > rbase)     sacc[nt][0] = -1e30f;
                if (cb + 1 > rbase)     sacc[nt][1] = -1e30f;
                if (cb     > rbase + 8) sacc[nt][2] = -1e30f;
                if (cb + 1 > rbase + 8) sacc[nt][3] = -1e30f;
            }
        }

        float mx0 = -1e30f, mx1 = -1e30f;
        #pragma unroll
        for (int nt = 0; nt < 8; ++nt) {
            mx0 = fmaxf(mx0, fmaxf(sacc[nt][0], sacc[nt][1]));
            mx1 = fmaxf(mx1, fmaxf(sacc[nt][2], sacc[nt][3]));
        }
        mx0 = fmaxf(mx0, __shfl_xor_sync(0xffffffffu, mx0, 1));
        mx0 = fmaxf(mx0, __shfl_xor_sync(0xffffffffu, mx0, 2));
        mx1 = fmaxf(mx1, __shfl_xor_sync(0xffffffffu, mx1, 1));
        mx1 = fmaxf(mx1, __shfl_xor_sync(0xffffffffu, mx1, 2));

        float mn0 = fmaxf(m0s, mx0), mn1 = fmaxf(m1s, mx1);
        float al0 = __expf(m0s - mn0), al1 = __expf(m1s - mn1);
        m0s = mn0; m1s = mn1;

        float sum0 = 0.0f, sum1 = 0.0f;
        #pragma unroll
        for (int nt = 0; nt < 8; ++nt) {
            float p0 = __expf(sacc[nt][0] - mn0);
            float p1 = __expf(sacc[nt][1] - mn0);
            float p2 = __expf(sacc[nt][2] - mn1);
            float p3 = __expf(sacc[nt][3] - mn1);
            sum0 += p0 + p1; sum1 += p2 + p3;
            float* pr0 = sP + prow * AP + nt * 8;
            float* pr1 = sP + (prow + 8) * AP + nt * 8;
            pr0[s0] = rna(p0); pr0[s1] = rna(p1);
            pr1[s0] = rna(p2); pr1[s1] = rna(p3);
        }
        sum0 += __shfl_xor_sync(0xffffffffu, sum0, 1);
        sum0 += __shfl_xor_sync(0xffffffffu, sum0, 2);
        sum1 += __shfl_xor_sync(0xffffffffu, sum1, 1);
        sum1 += __shfl_xor_sync(0xffffffffu, sum1, 2);
        l0s = l0s * al0 + sum0;
        l1s = l1s * al1 + sum1;
        #pragma unroll
        for (int nt = 0; nt < 8; ++nt) {
            oacc[nt][0] *= al0; oacc[nt][1] *= al0;
            oacc[nt][2] *= al1; oacc[nt][3] *= al1;
        }
        __syncwarp();   // sP rows are warp-private: warp fence suffices

        // O += P @ V
        #pragma unroll
        for (int kf = 0; kf < 8; ++kf) {
            const float* p = sP + (warp * 16) * AP + kf * 8 + 2 * tig;
            float2 x0 = *(const float2*)(p + g * AP);
            float2 x1 = *(const float2*)(p + (g + 8) * AP);
            unsigned a0 = fau(x0.x), a1 = fau(x1.x), a2 = fau(x0.y), a3 = fau(x1.y);
            #pragma unroll
            for (int nt = 0; nt < 8; ++nt) {
                float2 bv = *(const float2*)(cV + (nt * 8 + g) * AP + kf * 8 + 2 * tig);
                mma8(oacc[nt], a0, a1, a2, a3, fau(bv.x), fau(bv.y));
            }
        }
        // no trailing barrier (same ordering argument as the GEMM loop)
    }

    // epilogue -> g_y (tf32-rounded, c-permuted for proj GEMM)
    const int row = q0 + warp * 16 + g;
    const float inv0 = 1.0f / l0s, inv1 = 1.0f / l1s;
    #pragma unroll
    for (int nt = 0; nt < 8; ++nt) {
        int colb = hh * 64 + nt * 8;
        float* y0 = g_y + ((long)bb * T_ + row) * C_ + colb;
        float* y1 = g_y + ((long)bb * T_ + row + 8) * C_ + colb;
        y0[s0] = rna(oacc[nt][0] * inv0); y0[s1] = rna(oacc[nt][1] * inv0);
        y1[s0] = rna(oacc[nt][2] * inv1); y1[s1] = rna(oacc[nt][3] * inv1);
    }
}

// ---------------------------------------------------------------------------
extern "C" void kernel_launch(void* const* d_in, const int* in_sizes, int n_in,
                              void* d_out, int out_size)
{
    const float* x      = (const float*)d_in[0];
    const float* w_attn = (const float*)d_in[1];
    const float* b_attn = (const float*)d_in[2];
    const float* w_proj = (const float*)d_in[3];
    const float* b_proj = (const float*)d_in[4];
    float* out = (float*)d_out;

    float *xr, *wat, *wpt, *yy;
    cudaGetSymbolAddress((void**)&xr,  g_xr);
    cudaGetSymbolAddress((void**)&wat, g_wat);
    cudaGetSymbolAddress((void**)&wpt, g_wpt);
    cudaGetSymbolAddress((void**)&yy,  g_y);

    cudaFuncSetAttribute(gemm_kernel,
                         cudaFuncAttributeMaxDynamicSharedMemorySize, GEMM_SMEM);
    cudaFuncSetAttribute(attn_kernel,
                         cudaFuncAttributeMaxDynamicSharedMemorySize, ATT_SMEM);

    roundperm_kernel<<<512, 256>>>(x, xr, M_ * C_ / 8);
    transpose_round_kernel<<<dim3(N3_ / 32, C_ / 32), dim3(32, 8)>>>(w_attn, wat, C_, N3_);
    transpose_round_kernel<<<dim3(C_ / 32, C_ / 32), dim3(32, 8)>>>(w_proj, wpt, C_, C_);

    gemm_kernel<<<dim3(N3_ / 128, M_ / 128), 256, GEMM_SMEM>>>(xr, wat, b_attn, nullptr, 0);
    attn_kernel<<<dim3(T_ / 128, BH_), 256, ATT_SMEM>>>();
    gemm_kernel<<<dim3(C_ / 128, M_ / 128), 256, GEMM_SMEM>>>(yy, wpt, b_proj, out, 1);
}